// round 2
// baseline (speedup 1.0000x reference)
#include <cuda_runtime.h>
#include <cstdint>
#include <cstddef>

#define BB 2
#define TT 2048
#define CC 2048
#define HH 16
#define HD 128
#define TC3 6144   // 3*CC

// Scratch: qkv projection output and attention output (pre-proj).
__device__ float g_qkv[(size_t)BB * TT * TC3];   // ~100 MB
__device__ float g_y[(size_t)BB * TT * CC];      // ~33 MB

// ---------------------------------------------------------------------------
// NT SGEMM: C[M][N] = A[M][K] * B[N][K]^T   (both operands K-contiguous)
// 128x128 block tile, BK=16, 256 threads, 8x8 per-thread microtile
// ---------------------------------------------------------------------------
#define BM 128
#define BN 128
#define BK 16

__global__ __launch_bounds__(256) void sgemm_nt(const float* __restrict__ A,
                                                const float* __restrict__ Bm,
                                                float* __restrict__ Cg,
                                                int M, int N, int K) {
    __shared__ float As[BK][BM + 4];
    __shared__ float Bs[BK][BN + 4];
    const int tid = threadIdx.x;
    const int bm = blockIdx.y * BM;
    const int bn = blockIdx.x * BN;
    const int tx = tid & 15;
    const int ty = tid >> 4;

    float acc[8][8];
#pragma unroll
    for (int i = 0; i < 8; ++i)
#pragma unroll
        for (int j = 0; j < 8; ++j) acc[i][j] = 0.f;

    for (int kt = 0; kt < K; kt += BK) {
#pragma unroll
        for (int it = 0; it < 2; ++it) {
            int idx = tid + it * 256;      // 0..511 float4 slots
            int row = idx >> 2;            // 0..127
            int kq = (idx & 3) << 2;       // 0,4,8,12
            float4 av = *(const float4*)&A[(size_t)(bm + row) * K + kt + kq];
            As[kq + 0][row] = av.x; As[kq + 1][row] = av.y;
            As[kq + 2][row] = av.z; As[kq + 3][row] = av.w;
            float4 bv = *(const float4*)&Bm[(size_t)(bn + row) * K + kt + kq];
            Bs[kq + 0][row] = bv.x; Bs[kq + 1][row] = bv.y;
            Bs[kq + 2][row] = bv.z; Bs[kq + 3][row] = bv.w;
        }
        __syncthreads();
#pragma unroll
        for (int k = 0; k < BK; ++k) {
            float a[8], b[8];
            *(float4*)&a[0] = *(const float4*)&As[k][ty * 4];
            *(float4*)&a[4] = *(const float4*)&As[k][64 + ty * 4];
            *(float4*)&b[0] = *(const float4*)&Bs[k][tx * 4];
            *(float4*)&b[4] = *(const float4*)&Bs[k][64 + tx * 4];
#pragma unroll
            for (int i = 0; i < 8; ++i)
#pragma unroll
                for (int j = 0; j < 8; ++j) acc[i][j] += a[i] * b[j];
        }
        __syncthreads();
    }

#pragma unroll
    for (int ih = 0; ih < 2; ++ih)
#pragma unroll
        for (int i = 0; i < 4; ++i) {
            int row = bm + ih * 64 + ty * 4 + i;
#pragma unroll
            for (int jh = 0; jh < 2; ++jh) {
                int col = bn + jh * 64 + tx * 4;
                float4 v;
                v.x = acc[ih * 4 + i][jh * 4 + 0];
                v.y = acc[ih * 4 + i][jh * 4 + 1];
                v.z = acc[ih * 4 + i][jh * 4 + 2];
                v.w = acc[ih * 4 + i][jh * 4 + 3];
                *(float4*)&Cg[(size_t)row * N + col] = v;
            }
        }
}

// ---------------------------------------------------------------------------
// Flash attention (fp32): one block = (b, h, 64-row q tile). BK tile = 64.
// Q,K stored d-major (transposed) in smem for conflict-free S outer product.
// ---------------------------------------------------------------------------
struct AttnSmem {
    float Qt[HD][68];     // Qt[d][r], pre-scaled by 1/sqrt(hd)
    float Kt[HD][68];     // Kt[d][c]
    float Vs[64][132];    // Vs[c][d]
    float Ss[64][65];     // scores / probabilities
    float m_s[64];
    float l_s[64];
    float alpha_s[64];
};

__global__ __launch_bounds__(256) void attn_kernel(const float* __restrict__ qkv,
                                                   float* __restrict__ y) {
    extern __shared__ char smem_raw[];
    AttnSmem& sm = *reinterpret_cast<AttnSmem*>(smem_raw);
    const int tid = threadIdx.x;
    const int qb = (int)gridDim.x - 1 - (int)blockIdx.x;  // heavy tiles first
    const int bh = blockIdx.y;
    const int b = bh >> 4;
    const int h = bh & 15;
    const float scale = 0.08838834764831845f;  // 1/sqrt(128)
    const size_t base = (size_t)b * TT * TC3 + (size_t)h * HD;

    // Load Q tile (pre-scaled), transposed into Qt[d][r]
#pragma unroll
    for (int i = 0; i < 8; ++i) {
        int idx4 = tid + i * 256;      // 0..2047 float4s
        int r = idx4 >> 5;             // 0..63
        int d4 = (idx4 & 31) << 2;     // 0..124 step 4
        float4 qv = *(const float4*)&qkv[base + (size_t)(qb * 64 + r) * TC3 + d4];
        sm.Qt[d4 + 0][r] = qv.x * scale;
        sm.Qt[d4 + 1][r] = qv.y * scale;
        sm.Qt[d4 + 2][r] = qv.z * scale;
        sm.Qt[d4 + 3][r] = qv.w * scale;
    }
    if (tid < 64) { sm.m_s[tid] = -1e30f; sm.l_s[tid] = 0.f; }

    // O accumulator mapping: 2 rows x 16 cols per thread
    const int rp = tid >> 3;          // 0..31 -> rows {2rp, 2rp+1}
    const int dg = tid & 7;           // d = dg*4 + k*32 + j
    float o[2][4][4];
#pragma unroll
    for (int rr = 0; rr < 2; ++rr)
#pragma unroll
        for (int k = 0; k < 4; ++k)
#pragma unroll
            for (int j = 0; j < 4; ++j) o[rr][k][j] = 0.f;

    // S-compute mapping: 4x4 microtile
    const int r0 = (tid >> 4) << 2;
    const int c0 = (tid & 15) << 2;

    for (int kb = 0; kb <= qb; ++kb) {
        __syncthreads();  // previous PV done before K/V overwrite
        // Load K (transposed) and V tiles
#pragma unroll
        for (int i = 0; i < 8; ++i) {
            int idx4 = tid + i * 256;
            int c = idx4 >> 5;
            int d4 = (idx4 & 31) << 2;
            size_t g = base + (size_t)(kb * 64 + c) * TC3 + d4;
            float4 kv = *(const float4*)&qkv[g + CC];
            sm.Kt[d4 + 0][c] = kv.x;
            sm.Kt[d4 + 1][c] = kv.y;
            sm.Kt[d4 + 2][c] = kv.z;
            sm.Kt[d4 + 3][c] = kv.w;
            float4 vv = *(const float4*)&qkv[g + 2 * CC];
            *(float4*)&sm.Vs[c][d4] = vv;
        }
        __syncthreads();

        // S = (Q*scale) K^T, 4x4 outer product over d
        float acc[4][4];
#pragma unroll
        for (int i = 0; i < 4; ++i)
#pragma unroll
            for (int j = 0; j < 4; ++j) acc[i][j] = 0.f;

        for (int kk = 0; kk < HD; kk += 4) {
#pragma unroll
            for (int ik = 0; ik < 4; ++ik) {
                float qv[4], kv[4];
                *(float4*)qv = *(const float4*)&sm.Qt[kk + ik][r0];
                *(float4*)kv = *(const float4*)&sm.Kt[kk + ik][c0];
#pragma unroll
                for (int i = 0; i < 4; ++i)
#pragma unroll
                    for (int j = 0; j < 4; ++j) acc[i][j] += qv[i] * kv[j];
            }
        }

        const bool diag = (kb == qb);
#pragma unroll
        for (int i = 0; i < 4; ++i)
#pragma unroll
            for (int j = 0; j < 4; ++j) {
                float s = acc[i][j];
                if (diag && (c0 + j) > (r0 + i)) s = -1e30f;
                sm.Ss[r0 + i][c0 + j] = s;
            }
        __syncthreads();

        // Online softmax per row (64 threads)
        if (tid < 64) {
            const int r = tid;
            float mx = -1e30f;
#pragma unroll 8
            for (int c = 0; c < 64; ++c) mx = fmaxf(mx, sm.Ss[r][c]);
            float m_old = sm.m_s[r];
            float m_new = fmaxf(m_old, mx);
            float alpha = __expf(m_old - m_new);
            float l = alpha * sm.l_s[r];
#pragma unroll 8
            for (int c = 0; c < 64; ++c) {
                float p = __expf(sm.Ss[r][c] - m_new);
                sm.Ss[r][c] = p;
                l += p;
            }
            sm.m_s[r] = m_new;
            sm.l_s[r] = l;
            sm.alpha_s[r] = alpha;
        }
        __syncthreads();

        // O = O*alpha + P @ V
        const float a0 = sm.alpha_s[rp * 2];
        const float a1 = sm.alpha_s[rp * 2 + 1];
#pragma unroll
        for (int k = 0; k < 4; ++k)
#pragma unroll
            for (int j = 0; j < 4; ++j) { o[0][k][j] *= a0; o[1][k][j] *= a1; }

#pragma unroll 4
        for (int c = 0; c < 64; ++c) {
            float p0 = sm.Ss[rp * 2][c];
            float p1 = sm.Ss[rp * 2 + 1][c];
#pragma unroll
            for (int k = 0; k < 4; ++k) {
                float v[4];
                *(float4*)v = *(const float4*)&sm.Vs[c][dg * 4 + k * 32];
#pragma unroll
                for (int j = 0; j < 4; ++j) {
                    o[0][k][j] += p0 * v[j];
                    o[1][k][j] += p1 * v[j];
                }
            }
        }
    }

    // Epilogue: normalize and write y[b][t][h*HD + d]
    const float inv0 = 1.0f / sm.l_s[rp * 2];
    const float inv1 = 1.0f / sm.l_s[rp * 2 + 1];
#pragma unroll
    for (int rr = 0; rr < 2; ++rr) {
        int trow = qb * 64 + rp * 2 + rr;
        float inv = rr ? inv1 : inv0;
#pragma unroll
        for (int k = 0; k < 4; ++k) {
            float4 v;
            v.x = o[rr][k][0] * inv;
            v.y = o[rr][k][1] * inv;
            v.z = o[rr][k][2] * inv;
            v.w = o[rr][k][3] * inv;
            *(float4*)&y[(size_t)b * TT * CC + (size_t)trow * CC + h * HD + dg * 4 + k * 32] = v;
        }
    }
}

// ---------------------------------------------------------------------------
extern "C" void kernel_launch(void* const* d_in, const int* in_sizes, int n_in,
                              void* d_out, int out_size) {
    const float* x = (const float*)d_in[0];        // [B,T,C]
    const float* w_attn = (const float*)d_in[1];   // [3C,C]
    const float* w_proj = (const float*)d_in[2];   // [C,C]
    float* out = (float*)d_out;                    // [B,T,C]

    float* qkv = nullptr;
    float* y = nullptr;
    cudaGetSymbolAddress((void**)&qkv, g_qkv);
    cudaGetSymbolAddress((void**)&y, g_y);

    cudaFuncSetAttribute(attn_kernel, cudaFuncAttributeMaxDynamicSharedMemorySize,
                         (int)sizeof(AttnSmem));

    // 1) QKV projection: [4096,2048] x [6144,2048]^T -> [4096,6144]
    sgemm_nt<<<dim3(TC3 / BN, (BB * TT) / BM), 256>>>(x, w_attn, qkv, BB * TT, TC3, CC);

    // 2) Causal flash attention -> y [B,T,C]
    attn_kernel<<<dim3(TT / 64, BB * HH), 256, sizeof(AttnSmem)>>>(qkv, y);

    // 3) Output projection: [4096,2048] x [2048,2048]^T -> out
    sgemm_nt<<<dim3(CC / BN, (BB * TT) / BM), 256>>>(y, w_proj, out, BB * TT, CC, CC);
}

// round 3
// speedup vs baseline: 2.5059x; 2.5059x over previous
#include <cuda_runtime.h>
#include <cuda_bf16.h>
#include <cstdint>
#include <cstddef>

#define BB 2
#define TT 2048
#define CC 2048
#define HH 16
#define HD 128
#define TC3 6144   // 3*CC

// fp32 scratch
__device__ float g_qkv[(size_t)BB * TT * TC3];   // ~100 MB
__device__ float g_y[(size_t)BB * TT * CC];      // ~33 MB

// bf16 split scratch (hi/lo)
__device__ __nv_bfloat16 g_x_hi[(size_t)BB * TT * CC];
__device__ __nv_bfloat16 g_x_lo[(size_t)BB * TT * CC];
__device__ __nv_bfloat16 g_wa_hi[(size_t)TC3 * CC];
__device__ __nv_bfloat16 g_wa_lo[(size_t)TC3 * CC];
__device__ __nv_bfloat16 g_wp_hi[(size_t)CC * CC];
__device__ __nv_bfloat16 g_wp_lo[(size_t)CC * CC];
__device__ __nv_bfloat16 g_y_hi[(size_t)BB * TT * CC];
__device__ __nv_bfloat16 g_y_lo[(size_t)BB * TT * CC];

// ---------------------------------------------------------------------------
// fp32 -> (hi, lo) bf16 split. lo = bf16(x - f32(hi)).
// ---------------------------------------------------------------------------
__global__ __launch_bounds__(256) void split_kernel(const float* __restrict__ src,
                                                    __nv_bfloat16* __restrict__ hi,
                                                    __nv_bfloat16* __restrict__ lo,
                                                    int n) {
    int i = (blockIdx.x * blockDim.x + threadIdx.x) * 4;
    if (i >= n) return;
    float4 v = *(const float4*)(src + i);
    __nv_bfloat16 h0 = __float2bfloat16(v.x);
    __nv_bfloat16 h1 = __float2bfloat16(v.y);
    __nv_bfloat16 h2 = __float2bfloat16(v.z);
    __nv_bfloat16 h3 = __float2bfloat16(v.w);
    __nv_bfloat16 l0 = __float2bfloat16(v.x - __bfloat162float(h0));
    __nv_bfloat16 l1 = __float2bfloat16(v.y - __bfloat162float(h1));
    __nv_bfloat16 l2 = __float2bfloat16(v.z - __bfloat162float(h2));
    __nv_bfloat16 l3 = __float2bfloat16(v.w - __bfloat162float(h3));
    __nv_bfloat162 hp0; hp0.x = h0; hp0.y = h1;
    __nv_bfloat162 hp1; hp1.x = h2; hp1.y = h3;
    __nv_bfloat162 lp0; lp0.x = l0; lp0.y = l1;
    __nv_bfloat162 lp1; lp1.x = l2; lp1.y = l3;
    *(__nv_bfloat162*)(hi + i) = hp0;
    *(__nv_bfloat162*)(hi + i + 2) = hp1;
    *(__nv_bfloat162*)(lo + i) = lp0;
    *(__nv_bfloat162*)(lo + i + 2) = lp1;
}

// ---------------------------------------------------------------------------
// bf16-split NT GEMM on tensor cores:
//   C[M][N](fp32) = (Ah+Al)[M][K] * (Bh+Bl)[N][K]^T, 3 MMA products.
// 128x128x32 block tile, 256 thr = 8 warps (2x4), warp tile 64x32,
// mma.sync.m16n8k16 bf16, cp.async double-buffered smem (row stride 40 halfs).
// ---------------------------------------------------------------------------
#define GBM 128
#define GBN 128
#define GBK 32
#define ASTRIDE 40
#define TILE_HALFS (128 * ASTRIDE)

__device__ __forceinline__ void cp16(void* smem_ptr, const void* gptr) {
    uint32_t s = (uint32_t)__cvta_generic_to_shared(smem_ptr);
    asm volatile("cp.async.ca.shared.global [%0], [%1], 16;\n" :: "r"(s), "l"(gptr));
}

__device__ __forceinline__ void mma16816(float* d, const uint32_t* a, const uint32_t* b) {
    asm volatile(
        "mma.sync.aligned.m16n8k16.row.col.f32.bf16.bf16.f32 "
        "{%0,%1,%2,%3}, {%4,%5,%6,%7}, {%8,%9}, {%0,%1,%2,%3};\n"
        : "+f"(d[0]), "+f"(d[1]), "+f"(d[2]), "+f"(d[3])
        : "r"(a[0]), "r"(a[1]), "r"(a[2]), "r"(a[3]), "r"(b[0]), "r"(b[1]));
}

__global__ __launch_bounds__(256) void gemm_bf16split(
    const __nv_bfloat16* __restrict__ Ah, const __nv_bfloat16* __restrict__ Al,
    const __nv_bfloat16* __restrict__ Bh, const __nv_bfloat16* __restrict__ Bl,
    float* __restrict__ Cg, int M, int N, int K) {
    extern __shared__ __nv_bfloat16 sm[];
    const int tid = threadIdx.x;
    const int lane = tid & 31;
    const int warp = tid >> 5;
    const int wm = warp >> 2;        // 0..1
    const int wn = warp & 3;         // 0..3
    const int bm = blockIdx.y * GBM;
    const int bn = blockIdx.x * GBN;

    float acc[4][4][4];
#pragma unroll
    for (int mt = 0; mt < 4; ++mt)
#pragma unroll
        for (int nt = 0; nt < 4; ++nt)
#pragma unroll
            for (int r = 0; r < 4; ++r) acc[mt][nt][r] = 0.f;

    const __nv_bfloat16* gbase[4] = {Ah, Al, Bh, Bl};

    auto load_stage = [&](int buf, int k0) {
#pragma unroll
        for (int arr = 0; arr < 4; ++arr) {
            int rowoff = (arr < 2) ? bm : bn;
            const __nv_bfloat16* g = gbase[arr];
#pragma unroll
            for (int half = 0; half < 2; ++half) {
                int w = tid + half * 256;       // 0..511
                int row = w >> 2;               // 0..127
                int ck = (w & 3) * 8;           // 0,8,16,24 (bf16 units)
                cp16(&sm[(size_t)(buf * 4 + arr) * TILE_HALFS + row * ASTRIDE + ck],
                     g + (size_t)(rowoff + row) * K + k0 + ck);
            }
        }
    };

    const int nk = K / GBK;
    load_stage(0, 0);
    asm volatile("cp.async.commit_group;\n");

    for (int kt = 0; kt < nk; ++kt) {
        const int buf = kt & 1;
        if (kt + 1 < nk) {
            load_stage(buf ^ 1, (kt + 1) * GBK);
            asm volatile("cp.async.commit_group;\n");
            asm volatile("cp.async.wait_group 1;\n");
        } else {
            asm volatile("cp.async.wait_group 0;\n");
        }
        __syncthreads();

        const uint32_t* Ahs = (const uint32_t*)&sm[(size_t)(buf * 4 + 0) * TILE_HALFS];
        const uint32_t* Als = (const uint32_t*)&sm[(size_t)(buf * 4 + 1) * TILE_HALFS];
        const uint32_t* Bhs = (const uint32_t*)&sm[(size_t)(buf * 4 + 2) * TILE_HALFS];
        const uint32_t* Bls = (const uint32_t*)&sm[(size_t)(buf * 4 + 3) * TILE_HALFS];

#pragma unroll
        for (int k16 = 0; k16 < 2; ++k16) {
            const int cA = k16 * 8 + (lane & 3);   // 32-bit col index (pairs)
            uint32_t bh[4][2], bl[4][2];
#pragma unroll
            for (int nt = 0; nt < 4; ++nt) {
                int nrow = wn * 32 + nt * 8 + (lane >> 2);
                bh[nt][0] = Bhs[nrow * 20 + cA];
                bh[nt][1] = Bhs[nrow * 20 + cA + 4];
                bl[nt][0] = Bls[nrow * 20 + cA];
                bl[nt][1] = Bls[nrow * 20 + cA + 4];
            }
#pragma unroll
            for (int mt = 0; mt < 4; ++mt) {
                int r = wm * 64 + mt * 16 + (lane >> 2);
                uint32_t ah[4], al[4];
                ah[0] = Ahs[r * 20 + cA];
                ah[1] = Ahs[(r + 8) * 20 + cA];
                ah[2] = Ahs[r * 20 + cA + 4];
                ah[3] = Ahs[(r + 8) * 20 + cA + 4];
                al[0] = Als[r * 20 + cA];
                al[1] = Als[(r + 8) * 20 + cA];
                al[2] = Als[r * 20 + cA + 4];
                al[3] = Als[(r + 8) * 20 + cA + 4];
#pragma unroll
                for (int nt = 0; nt < 4; ++nt) {
                    mma16816(acc[mt][nt], ah, bh[nt]);
                    mma16816(acc[mt][nt], ah, bl[nt]);
                    mma16816(acc[mt][nt], al, bh[nt]);
                }
            }
        }
        __syncthreads();
    }

    // Epilogue: fp32 direct to global
#pragma unroll
    for (int mt = 0; mt < 4; ++mt) {
        int r = bm + wm * 64 + mt * 16 + (lane >> 2);
#pragma unroll
        for (int nt = 0; nt < 4; ++nt) {
            int c = bn + wn * 32 + nt * 8 + 2 * (lane & 3);
            float2 v0 = make_float2(acc[mt][nt][0], acc[mt][nt][1]);
            float2 v1 = make_float2(acc[mt][nt][2], acc[mt][nt][3]);
            *(float2*)&Cg[(size_t)r * N + c] = v0;
            *(float2*)&Cg[(size_t)(r + 8) * N + c] = v1;
        }
    }
}

// ---------------------------------------------------------------------------
// Flash attention (fp32) — unchanged from R2.
// ---------------------------------------------------------------------------
struct AttnSmem {
    float Qt[HD][68];
    float Kt[HD][68];
    float Vs[64][132];
    float Ss[64][65];
    float m_s[64];
    float l_s[64];
    float alpha_s[64];
};

__global__ __launch_bounds__(256) void attn_kernel(const float* __restrict__ qkv,
                                                   float* __restrict__ y) {
    extern __shared__ char smem_raw[];
    AttnSmem& sm = *reinterpret_cast<AttnSmem*>(smem_raw);
    const int tid = threadIdx.x;
    const int qb = (int)gridDim.x - 1 - (int)blockIdx.x;
    const int bh = blockIdx.y;
    const int b = bh >> 4;
    const int h = bh & 15;
    const float scale = 0.08838834764831845f;
    const size_t base = (size_t)b * TT * TC3 + (size_t)h * HD;

#pragma unroll
    for (int i = 0; i < 8; ++i) {
        int idx4 = tid + i * 256;
        int r = idx4 >> 5;
        int d4 = (idx4 & 31) << 2;
        float4 qv = *(const float4*)&qkv[base + (size_t)(qb * 64 + r) * TC3 + d4];
        sm.Qt[d4 + 0][r] = qv.x * scale;
        sm.Qt[d4 + 1][r] = qv.y * scale;
        sm.Qt[d4 + 2][r] = qv.z * scale;
        sm.Qt[d4 + 3][r] = qv.w * scale;
    }
    if (tid < 64) { sm.m_s[tid] = -1e30f; sm.l_s[tid] = 0.f; }

    const int rp = tid >> 3;
    const int dg = tid & 7;
    float o[2][4][4];
#pragma unroll
    for (int rr = 0; rr < 2; ++rr)
#pragma unroll
        for (int k = 0; k < 4; ++k)
#pragma unroll
            for (int j = 0; j < 4; ++j) o[rr][k][j] = 0.f;

    const int r0 = (tid >> 4) << 2;
    const int c0 = (tid & 15) << 2;

    for (int kb = 0; kb <= qb; ++kb) {
        __syncthreads();
#pragma unroll
        for (int i = 0; i < 8; ++i) {
            int idx4 = tid + i * 256;
            int c = idx4 >> 5;
            int d4 = (idx4 & 31) << 2;
            size_t g = base + (size_t)(kb * 64 + c) * TC3 + d4;
            float4 kv = *(const float4*)&qkv[g + CC];
            sm.Kt[d4 + 0][c] = kv.x;
            sm.Kt[d4 + 1][c] = kv.y;
            sm.Kt[d4 + 2][c] = kv.z;
            sm.Kt[d4 + 3][c] = kv.w;
            float4 vv = *(const float4*)&qkv[g + 2 * CC];
            *(float4*)&sm.Vs[c][d4] = vv;
        }
        __syncthreads();

        float acc[4][4];
#pragma unroll
        for (int i = 0; i < 4; ++i)
#pragma unroll
            for (int j = 0; j < 4; ++j) acc[i][j] = 0.f;

        for (int kk = 0; kk < HD; kk += 4) {
#pragma unroll
            for (int ik = 0; ik < 4; ++ik) {
                float qv[4], kv[4];
                *(float4*)qv = *(const float4*)&sm.Qt[kk + ik][r0];
                *(float4*)kv = *(const float4*)&sm.Kt[kk + ik][c0];
#pragma unroll
                for (int i = 0; i < 4; ++i)
#pragma unroll
                    for (int j = 0; j < 4; ++j) acc[i][j] += qv[i] * kv[j];
            }
        }

        const bool diag = (kb == qb);
#pragma unroll
        for (int i = 0; i < 4; ++i)
#pragma unroll
            for (int j = 0; j < 4; ++j) {
                float s = acc[i][j];
                if (diag && (c0 + j) > (r0 + i)) s = -1e30f;
                sm.Ss[r0 + i][c0 + j] = s;
            }
        __syncthreads();

        if (tid < 64) {
            const int r = tid;
            float mx = -1e30f;
#pragma unroll 8
            for (int c = 0; c < 64; ++c) mx = fmaxf(mx, sm.Ss[r][c]);
            float m_old = sm.m_s[r];
            float m_new = fmaxf(m_old, mx);
            float alpha = __expf(m_old - m_new);
            float l = alpha * sm.l_s[r];
#pragma unroll 8
            for (int c = 0; c < 64; ++c) {
                float p = __expf(sm.Ss[r][c] - m_new);
                sm.Ss[r][c] = p;
                l += p;
            }
            sm.m_s[r] = m_new;
            sm.l_s[r] = l;
            sm.alpha_s[r] = alpha;
        }
        __syncthreads();

        const float a0 = sm.alpha_s[rp * 2];
        const float a1 = sm.alpha_s[rp * 2 + 1];
#pragma unroll
        for (int k = 0; k < 4; ++k)
#pragma unroll
            for (int j = 0; j < 4; ++j) { o[0][k][j] *= a0; o[1][k][j] *= a1; }

#pragma unroll 4
        for (int c = 0; c < 64; ++c) {
            float p0 = sm.Ss[rp * 2][c];
            float p1 = sm.Ss[rp * 2 + 1][c];
#pragma unroll
            for (int k = 0; k < 4; ++k) {
                float v[4];
                *(float4*)v = *(const float4*)&sm.Vs[c][dg * 4 + k * 32];
#pragma unroll
                for (int j = 0; j < 4; ++j) {
                    o[0][k][j] += p0 * v[j];
                    o[1][k][j] += p1 * v[j];
                }
            }
        }
    }

    const float inv0 = 1.0f / sm.l_s[rp * 2];
    const float inv1 = 1.0f / sm.l_s[rp * 2 + 1];
#pragma unroll
    for (int rr = 0; rr < 2; ++rr) {
        int trow = qb * 64 + rp * 2 + rr;
        float inv = rr ? inv1 : inv0;
#pragma unroll
        for (int k = 0; k < 4; ++k) {
            float4 v;
            v.x = o[rr][k][0] * inv;
            v.y = o[rr][k][1] * inv;
            v.z = o[rr][k][2] * inv;
            v.w = o[rr][k][3] * inv;
            *(float4*)&y[(size_t)b * TT * CC + (size_t)trow * CC + h * HD + dg * 4 + k * 32] = v;
        }
    }
}

// ---------------------------------------------------------------------------
extern "C" void kernel_launch(void* const* d_in, const int* in_sizes, int n_in,
                              void* d_out, int out_size) {
    const float* x = (const float*)d_in[0];
    const float* w_attn = (const float*)d_in[1];
    const float* w_proj = (const float*)d_in[2];
    float* out = (float*)d_out;

    float *qkv, *y;
    __nv_bfloat16 *xh, *xl, *wah, *wal, *wph, *wpl, *yh, *yl;
    cudaGetSymbolAddress((void**)&qkv, g_qkv);
    cudaGetSymbolAddress((void**)&y, g_y);
    cudaGetSymbolAddress((void**)&xh, g_x_hi);
    cudaGetSymbolAddress((void**)&xl, g_x_lo);
    cudaGetSymbolAddress((void**)&wah, g_wa_hi);
    cudaGetSymbolAddress((void**)&wal, g_wa_lo);
    cudaGetSymbolAddress((void**)&wph, g_wp_hi);
    cudaGetSymbolAddress((void**)&wpl, g_wp_lo);
    cudaGetSymbolAddress((void**)&yh, g_y_hi);
    cudaGetSymbolAddress((void**)&yl, g_y_lo);

    const int gemm_smem = 2 * 4 * TILE_HALFS * (int)sizeof(__nv_bfloat16);  // 81920
    cudaFuncSetAttribute(gemm_bf16split, cudaFuncAttributeMaxDynamicSharedMemorySize, gemm_smem);
    cudaFuncSetAttribute(attn_kernel, cudaFuncAttributeMaxDynamicSharedMemorySize,
                         (int)sizeof(AttnSmem));

    const int nx = BB * TT * CC;      // 8.4M
    const int nwa = TC3 * CC;         // 12.6M
    const int nwp = CC * CC;          // 4.2M

    split_kernel<<<(nx / 4 + 255) / 256, 256>>>(x, xh, xl, nx);
    split_kernel<<<(nwa / 4 + 255) / 256, 256>>>(w_attn, wah, wal, nwa);
    split_kernel<<<(nwp / 4 + 255) / 256, 256>>>(w_proj, wph, wpl, nwp);

    // 1) QKV projection via tensor cores
    gemm_bf16split<<<dim3(TC3 / GBN, (BB * TT) / GBM), 256, gemm_smem>>>(
        xh, xl, wah, wal, qkv, BB * TT, TC3, CC);

    // 2) Causal flash attention
    attn_kernel<<<dim3(TT / 64, BB * HH), 256, sizeof(AttnSmem)>>>(qkv, y);

    // 3) Output projection
    split_kernel<<<(nx / 4 + 255) / 256, 256>>>(y, yh, yl, nx);
    gemm_bf16split<<<dim3(CC / GBN, (BB * TT) / GBM), 256, gemm_smem>>>(
        yh, yl, wph, wpl, out, BB * TT, CC, CC);
}

// round 4
// speedup vs baseline: 3.6590x; 1.4601x over previous
#include <cuda_runtime.h>
#include <cuda_bf16.h>
#include <cstdint>
#include <cstddef>

#define BB 2
#define TT 2048
#define CC 2048
#define HH 16
#define HD 128
#define TC3 6144   // 3*CC

// fp32 scratch (GEMM1 output)
__device__ float g_qkv[(size_t)BB * TT * TC3];   // ~100 MB

// bf16 split scratch for GEMM operands
__device__ __nv_bfloat16 g_x_hi[(size_t)BB * TT * CC];
__device__ __nv_bfloat16 g_x_lo[(size_t)BB * TT * CC];
__device__ __nv_bfloat16 g_wa_hi[(size_t)TC3 * CC];
__device__ __nv_bfloat16 g_wa_lo[(size_t)TC3 * CC];
__device__ __nv_bfloat16 g_wp_hi[(size_t)CC * CC];
__device__ __nv_bfloat16 g_wp_lo[(size_t)CC * CC];
__device__ __nv_bfloat16 g_y_hi[(size_t)BB * TT * CC];
__device__ __nv_bfloat16 g_y_lo[(size_t)BB * TT * CC];

// bf16 split attention operands
__device__ __nv_bfloat16 g_q_hi[(size_t)BB * HH * TT * HD];  // [b,h,t,d] (pre-scaled)
__device__ __nv_bfloat16 g_q_lo[(size_t)BB * HH * TT * HD];
__device__ __nv_bfloat16 g_k_hi[(size_t)BB * HH * TT * HD];  // [b,h,t,d]
__device__ __nv_bfloat16 g_k_lo[(size_t)BB * HH * TT * HD];
__device__ __nv_bfloat16 g_v_hi[(size_t)BB * HH * HD * TT];  // [b,h,d,t] transposed
__device__ __nv_bfloat16 g_v_lo[(size_t)BB * HH * HD * TT];

// ---------------------------------------------------------------------------
__global__ __launch_bounds__(256) void split_kernel(const float* __restrict__ src,
                                                    __nv_bfloat16* __restrict__ hi,
                                                    __nv_bfloat16* __restrict__ lo,
                                                    int n) {
    int i = (blockIdx.x * blockDim.x + threadIdx.x) * 4;
    if (i >= n) return;
    float4 v = *(const float4*)(src + i);
    __nv_bfloat16 h0 = __float2bfloat16(v.x);
    __nv_bfloat16 h1 = __float2bfloat16(v.y);
    __nv_bfloat16 h2 = __float2bfloat16(v.z);
    __nv_bfloat16 h3 = __float2bfloat16(v.w);
    __nv_bfloat162 hp0; hp0.x = h0; hp0.y = h1;
    __nv_bfloat162 hp1; hp1.x = h2; hp1.y = h3;
    __nv_bfloat162 lp0, lp1;
    lp0.x = __float2bfloat16(v.x - __bfloat162float(h0));
    lp0.y = __float2bfloat16(v.y - __bfloat162float(h1));
    lp1.x = __float2bfloat16(v.z - __bfloat162float(h2));
    lp1.y = __float2bfloat16(v.w - __bfloat162float(h3));
    *(__nv_bfloat162*)(hi + i) = hp0;
    *(__nv_bfloat162*)(hi + i + 2) = hp1;
    *(__nv_bfloat162*)(lo + i) = lp0;
    *(__nv_bfloat162*)(lo + i + 2) = lp1;
}

// Split Q or K from qkv [b,t,3C] into [b,h,t,d] bf16 hi/lo (optional scale).
__global__ __launch_bounds__(256) void split_qk(const float* __restrict__ qkv,
                                                __nv_bfloat16* __restrict__ hi,
                                                __nv_bfloat16* __restrict__ lo,
                                                int chan_off, float scale) {
    int idx4 = (blockIdx.x * blockDim.x + threadIdx.x) * 4;   // over [bh][t][d]
    int d = idx4 & 127;
    int t = (idx4 >> 7) & 2047;
    int bh = idx4 >> 18;
    int b = bh >> 4, h = bh & 15;
    const float* src = qkv + ((size_t)b * TT + t) * TC3 + chan_off + h * HD + d;
    float4 v = *(const float4*)src;
    v.x *= scale; v.y *= scale; v.z *= scale; v.w *= scale;
    __nv_bfloat16 h0 = __float2bfloat16(v.x);
    __nv_bfloat16 h1 = __float2bfloat16(v.y);
    __nv_bfloat16 h2 = __float2bfloat16(v.z);
    __nv_bfloat16 h3 = __float2bfloat16(v.w);
    __nv_bfloat162 hp0; hp0.x = h0; hp0.y = h1;
    __nv_bfloat162 hp1; hp1.x = h2; hp1.y = h3;
    __nv_bfloat162 lp0, lp1;
    lp0.x = __float2bfloat16(v.x - __bfloat162float(h0));
    lp0.y = __float2bfloat16(v.y - __bfloat162float(h1));
    lp1.x = __float2bfloat16(v.z - __bfloat162float(h2));
    lp1.y = __float2bfloat16(v.w - __bfloat162float(h3));
    *(__nv_bfloat162*)(hi + idx4) = hp0;
    *(__nv_bfloat162*)(hi + idx4 + 2) = hp1;
    *(__nv_bfloat162*)(lo + idx4) = lp0;
    *(__nv_bfloat162*)(lo + idx4 + 2) = lp1;
}

// Split+transpose V from qkv [b,t,3C] into [b,h,d,t] bf16 hi/lo. 32x32 tiles.
__global__ __launch_bounds__(256) void split_v_T(const float* __restrict__ qkv,
                                                 __nv_bfloat16* __restrict__ hi,
                                                 __nv_bfloat16* __restrict__ lo) {
    __shared__ float tile[32][33];
    int tx = threadIdx.x & 31;
    int ty = threadIdx.x >> 5;         // 0..7
    int t0 = blockIdx.x * 32;
    int d0 = blockIdx.y * 32;
    int bh = blockIdx.z;
    int b = bh >> 4, h = bh & 15;
#pragma unroll
    for (int i = 0; i < 4; ++i) {
        int t = t0 + ty + i * 8;
        tile[ty + i * 8][tx] = qkv[((size_t)b * TT + t) * TC3 + 2 * CC + h * HD + d0 + tx];
    }
    __syncthreads();
#pragma unroll
    for (int i = 0; i < 4; ++i) {
        int d = d0 + ty + i * 8;
        float v = tile[tx][ty + i * 8];
        __nv_bfloat16 hb = __float2bfloat16(v);
        __nv_bfloat16 lb = __float2bfloat16(v - __bfloat162float(hb));
        size_t dst = ((size_t)bh * HD + d) * TT + t0 + tx;
        hi[dst] = hb;
        lo[dst] = lb;
    }
}

// ---------------------------------------------------------------------------
// bf16-split NT GEMM on tensor cores (unchanged from R3).
// ---------------------------------------------------------------------------
#define GBM 128
#define GBN 128
#define GBK 32
#define ASTRIDE 40
#define TILE_HALFS (128 * ASTRIDE)

__device__ __forceinline__ void cp16(void* smem_ptr, const void* gptr) {
    uint32_t s = (uint32_t)__cvta_generic_to_shared(smem_ptr);
    asm volatile("cp.async.ca.shared.global [%0], [%1], 16;\n" :: "r"(s), "l"(gptr));
}

__device__ __forceinline__ void mma16816(float* d, const uint32_t* a, const uint32_t* b) {
    asm volatile(
        "mma.sync.aligned.m16n8k16.row.col.f32.bf16.bf16.f32 "
        "{%0,%1,%2,%3}, {%4,%5,%6,%7}, {%8,%9}, {%0,%1,%2,%3};\n"
        : "+f"(d[0]), "+f"(d[1]), "+f"(d[2]), "+f"(d[3])
        : "r"(a[0]), "r"(a[1]), "r"(a[2]), "r"(a[3]), "r"(b[0]), "r"(b[1]));
}

__global__ __launch_bounds__(256) void gemm_bf16split(
    const __nv_bfloat16* __restrict__ Ah, const __nv_bfloat16* __restrict__ Al,
    const __nv_bfloat16* __restrict__ Bh, const __nv_bfloat16* __restrict__ Bl,
    float* __restrict__ Cg, int M, int N, int K) {
    extern __shared__ __nv_bfloat16 sm[];
    const int tid = threadIdx.x;
    const int lane = tid & 31;
    const int warp = tid >> 5;
    const int wm = warp >> 2;
    const int wn = warp & 3;
    const int bm = blockIdx.y * GBM;
    const int bn = blockIdx.x * GBN;

    float acc[4][4][4];
#pragma unroll
    for (int mt = 0; mt < 4; ++mt)
#pragma unroll
        for (int nt = 0; nt < 4; ++nt)
#pragma unroll
            for (int r = 0; r < 4; ++r) acc[mt][nt][r] = 0.f;

    const __nv_bfloat16* gbase[4] = {Ah, Al, Bh, Bl};

    auto load_stage = [&](int buf, int k0) {
#pragma unroll
        for (int arr = 0; arr < 4; ++arr) {
            int rowoff = (arr < 2) ? bm : bn;
            const __nv_bfloat16* g = gbase[arr];
#pragma unroll
            for (int half = 0; half < 2; ++half) {
                int w = tid + half * 256;
                int row = w >> 2;
                int ck = (w & 3) * 8;
                cp16(&sm[(size_t)(buf * 4 + arr) * TILE_HALFS + row * ASTRIDE + ck],
                     g + (size_t)(rowoff + row) * K + k0 + ck);
            }
        }
    };

    const int nk = K / GBK;
    load_stage(0, 0);
    asm volatile("cp.async.commit_group;\n");

    for (int kt = 0; kt < nk; ++kt) {
        const int buf = kt & 1;
        if (kt + 1 < nk) {
            load_stage(buf ^ 1, (kt + 1) * GBK);
            asm volatile("cp.async.commit_group;\n");
            asm volatile("cp.async.wait_group 1;\n");
        } else {
            asm volatile("cp.async.wait_group 0;\n");
        }
        __syncthreads();

        const uint32_t* Ahs = (const uint32_t*)&sm[(size_t)(buf * 4 + 0) * TILE_HALFS];
        const uint32_t* Als = (const uint32_t*)&sm[(size_t)(buf * 4 + 1) * TILE_HALFS];
        const uint32_t* Bhs = (const uint32_t*)&sm[(size_t)(buf * 4 + 2) * TILE_HALFS];
        const uint32_t* Bls = (const uint32_t*)&sm[(size_t)(buf * 4 + 3) * TILE_HALFS];

#pragma unroll
        for (int k16 = 0; k16 < 2; ++k16) {
            const int cA = k16 * 8 + (lane & 3);
            uint32_t bh[4][2], bl[4][2];
#pragma unroll
            for (int nt = 0; nt < 4; ++nt) {
                int nrow = wn * 32 + nt * 8 + (lane >> 2);
                bh[nt][0] = Bhs[nrow * 20 + cA];
                bh[nt][1] = Bhs[nrow * 20 + cA + 4];
                bl[nt][0] = Bls[nrow * 20 + cA];
                bl[nt][1] = Bls[nrow * 20 + cA + 4];
            }
#pragma unroll
            for (int mt = 0; mt < 4; ++mt) {
                int r = wm * 64 + mt * 16 + (lane >> 2);
                uint32_t ah[4], al[4];
                ah[0] = Ahs[r * 20 + cA];
                ah[1] = Ahs[(r + 8) * 20 + cA];
                ah[2] = Ahs[r * 20 + cA + 4];
                ah[3] = Ahs[(r + 8) * 20 + cA + 4];
                al[0] = Als[r * 20 + cA];
                al[1] = Als[(r + 8) * 20 + cA];
                al[2] = Als[r * 20 + cA + 4];
                al[3] = Als[(r + 8) * 20 + cA + 4];
#pragma unroll
                for (int nt = 0; nt < 4; ++nt) {
                    mma16816(acc[mt][nt], ah, bh[nt]);
                    mma16816(acc[mt][nt], ah, bl[nt]);
                    mma16816(acc[mt][nt], al, bh[nt]);
                }
            }
        }
        __syncthreads();
    }

#pragma unroll
    for (int mt = 0; mt < 4; ++mt) {
        int r = bm + wm * 64 + mt * 16 + (lane >> 2);
#pragma unroll
        for (int nt = 0; nt < 4; ++nt) {
            int c = bn + wn * 32 + nt * 8 + 2 * (lane & 3);
            *(float2*)&Cg[(size_t)r * N + c] = make_float2(acc[mt][nt][0], acc[mt][nt][1]);
            *(float2*)&Cg[(size_t)(r + 8) * N + c] = make_float2(acc[mt][nt][2], acc[mt][nt][3]);
        }
    }
}

// ---------------------------------------------------------------------------
// Tensor-core flash attention. CTA = (b,h, 128-row q tile). K-tile = 64.
// 8 warps: wm = warp>>1 (q rows), wn = warp&1.
// ---------------------------------------------------------------------------
// smem byte offsets
#define OFF_QH 0
#define OFF_QL 34816
#define OFF_KH 69632
#define OFF_KL 87040
#define OFF_VH 104448
#define OFF_VL 122880
#define OFF_S  141312
#define OFF_PH 174592
#define OFF_PL 191488
#define OFF_M  208384
#define OFF_L  208896
#define OFF_AL 209408
#define ATTN_SMEM 209920
// strides
#define QSTR32 68   // 136 halfs
#define VSTR32 36   // 72 halfs
#define SSTRF  65
#define PSTR32 33   // 66 halfs

__global__ __launch_bounds__(256, 1) void attn_tc(
    const __nv_bfloat16* __restrict__ qh, const __nv_bfloat16* __restrict__ ql,
    const __nv_bfloat16* __restrict__ kh, const __nv_bfloat16* __restrict__ kl,
    const __nv_bfloat16* __restrict__ vh, const __nv_bfloat16* __restrict__ vl,
    __nv_bfloat16* __restrict__ yh, __nv_bfloat16* __restrict__ yl) {
    extern __shared__ char smb[];
    __nv_bfloat16* Qhs = (__nv_bfloat16*)(smb + OFF_QH);
    __nv_bfloat16* Qls = (__nv_bfloat16*)(smb + OFF_QL);
    __nv_bfloat16* Khs = (__nv_bfloat16*)(smb + OFF_KH);
    __nv_bfloat16* Kls = (__nv_bfloat16*)(smb + OFF_KL);
    __nv_bfloat16* Vhs = (__nv_bfloat16*)(smb + OFF_VH);
    __nv_bfloat16* Vls = (__nv_bfloat16*)(smb + OFF_VL);
    float* Ss = (float*)(smb + OFF_S);
    __nv_bfloat16* Phs = (__nv_bfloat16*)(smb + OFF_PH);
    __nv_bfloat16* Pls = (__nv_bfloat16*)(smb + OFF_PL);
    float* m_s = (float*)(smb + OFF_M);
    float* l_s = (float*)(smb + OFF_L);
    float* al_s = (float*)(smb + OFF_AL);

    const int tid = threadIdx.x;
    const int lane = tid & 31;
    const int warp = tid >> 5;
    const int wm = warp >> 1;          // 0..3 -> 32 q rows
    const int wn = warp & 1;           // 0..1
    const int qb = 15 - (int)blockIdx.x;
    const int bh = blockIdx.y;
    const int b = bh >> 4;
    const int h = bh & 15;

    // load Q tile (hi/lo), 16 cp16 per thread per array
    {
        const __nv_bfloat16* qsh = qh + ((size_t)bh * TT + qb * 128) * HD;
        const __nv_bfloat16* qsl = ql + ((size_t)bh * TT + qb * 128) * HD;
#pragma unroll
        for (int it = 0; it < 8; ++it) {
            int w = tid + it * 256;
            int row = w >> 4;
            int ck = (w & 15) * 8;
            cp16(Qhs + row * 136 + ck, qsh + (size_t)row * HD + ck);
            cp16(Qls + row * 136 + ck, qsl + (size_t)row * HD + ck);
        }
        asm volatile("cp.async.commit_group;\n");
    }
    if (tid < 128) { m_s[tid] = -1e30f; l_s[tid] = 0.f; }

    float O[2][8][4];
#pragma unroll
    for (int mt = 0; mt < 2; ++mt)
#pragma unroll
        for (int nt = 0; nt < 8; ++nt)
#pragma unroll
            for (int r = 0; r < 4; ++r) O[mt][nt][r] = 0.f;

    asm volatile("cp.async.wait_group 0;\n");
    __syncthreads();

    const int nkb = 2 * qb + 2;
    for (int kb = 0; kb < nkb; ++kb) {
        __syncthreads();  // prior PV / softmax reads done before overwrite
        // load K tile [64][128] and V tile [128][64] (hi/lo)
        {
            const __nv_bfloat16* ksh = kh + ((size_t)bh * TT + kb * 64) * HD;
            const __nv_bfloat16* ksl = kl + ((size_t)bh * TT + kb * 64) * HD;
#pragma unroll
            for (int it = 0; it < 4; ++it) {
                int w = tid + it * 256;
                int row = w >> 4;          // 0..63
                int ck = (w & 15) * 8;
                cp16(Khs + row * 136 + ck, ksh + (size_t)row * HD + ck);
                cp16(Kls + row * 136 + ck, ksl + (size_t)row * HD + ck);
            }
            const __nv_bfloat16* vsh = vh + (size_t)bh * HD * TT + kb * 64;
            const __nv_bfloat16* vsl = vl + (size_t)bh * HD * TT + kb * 64;
#pragma unroll
            for (int it = 0; it < 4; ++it) {
                int w = tid + it * 256;
                int row = w >> 3;          // 0..127 (d)
                int ck = (w & 7) * 8;
                cp16(Vhs + row * 72 + ck, vsh + (size_t)row * TT + ck);
                cp16(Vls + row * 72 + ck, vsl + (size_t)row * TT + ck);
            }
            asm volatile("cp.async.commit_group;\n");
            asm volatile("cp.async.wait_group 0;\n");
        }
        __syncthreads();

        // S = Q K^T (3 split products)
        float sa[2][4][4];
#pragma unroll
        for (int mt = 0; mt < 2; ++mt)
#pragma unroll
            for (int nt = 0; nt < 4; ++nt)
#pragma unroll
                for (int r = 0; r < 4; ++r) sa[mt][nt][r] = 0.f;

        const uint32_t* Qh32 = (const uint32_t*)Qhs;
        const uint32_t* Ql32 = (const uint32_t*)Qls;
        const uint32_t* Kh32 = (const uint32_t*)Khs;
        const uint32_t* Kl32 = (const uint32_t*)Kls;
#pragma unroll
        for (int k16 = 0; k16 < 8; ++k16) {
            const int cA = k16 * 8 + (lane & 3);
            uint32_t bhf[4][2], blf[4][2];
#pragma unroll
            for (int nt = 0; nt < 4; ++nt) {
                int n = wn * 32 + nt * 8 + (lane >> 2);
                bhf[nt][0] = Kh32[n * QSTR32 + cA];
                bhf[nt][1] = Kh32[n * QSTR32 + cA + 4];
                blf[nt][0] = Kl32[n * QSTR32 + cA];
                blf[nt][1] = Kl32[n * QSTR32 + cA + 4];
            }
#pragma unroll
            for (int mt = 0; mt < 2; ++mt) {
                int r = wm * 32 + mt * 16 + (lane >> 2);
                uint32_t ah[4], al[4];
                ah[0] = Qh32[r * QSTR32 + cA];
                ah[1] = Qh32[(r + 8) * QSTR32 + cA];
                ah[2] = Qh32[r * QSTR32 + cA + 4];
                ah[3] = Qh32[(r + 8) * QSTR32 + cA + 4];
                al[0] = Ql32[r * QSTR32 + cA];
                al[1] = Ql32[(r + 8) * QSTR32 + cA];
                al[2] = Ql32[r * QSTR32 + cA + 4];
                al[3] = Ql32[(r + 8) * QSTR32 + cA + 4];
#pragma unroll
                for (int nt = 0; nt < 4; ++nt) {
                    mma16816(sa[mt][nt], ah, bhf[nt]);
                    mma16816(sa[mt][nt], ah, blf[nt]);
                    mma16816(sa[mt][nt], al, bhf[nt]);
                }
            }
        }

        // mask + write S to smem
#pragma unroll
        for (int mt = 0; mt < 2; ++mt) {
#pragma unroll
            for (int nt = 0; nt < 4; ++nt) {
                int rl = wm * 32 + mt * 16 + (lane >> 2);
                int cl = wn * 32 + nt * 8 + 2 * (lane & 3);
                int gr = qb * 128 + rl;
                int gc = kb * 64 + cl;
                float s0 = (gc > gr) ? -1e30f : sa[mt][nt][0];
                float s1 = (gc + 1 > gr) ? -1e30f : sa[mt][nt][1];
                float s2 = (gc > gr + 8) ? -1e30f : sa[mt][nt][2];
                float s3 = (gc + 1 > gr + 8) ? -1e30f : sa[mt][nt][3];
                Ss[rl * SSTRF + cl] = s0;
                Ss[rl * SSTRF + cl + 1] = s1;
                Ss[(rl + 8) * SSTRF + cl] = s2;
                Ss[(rl + 8) * SSTRF + cl + 1] = s3;
            }
        }
        __syncthreads();

        // online softmax, one thread per row
        if (tid < 128) {
            const int r = tid;
            const float* Sr = Ss + r * SSTRF;
            float mx = -1e30f;
#pragma unroll 8
            for (int c = 0; c < 64; ++c) mx = fmaxf(mx, Sr[c]);
            float mo = m_s[r];
            float mn = fmaxf(mo, mx);
            float alpha = __expf(mo - mn);
            float l = alpha * l_s[r];
            __nv_bfloat162* Pr_h = (__nv_bfloat162*)(Phs + r * 66);
            __nv_bfloat162* Pr_l = (__nv_bfloat162*)(Pls + r * 66);
#pragma unroll 4
            for (int c = 0; c < 64; c += 2) {
                float p0 = __expf(Sr[c] - mn);
                float p1 = __expf(Sr[c + 1] - mn);
                l += p0 + p1;
                __nv_bfloat16 h0 = __float2bfloat16(p0);
                __nv_bfloat16 h1 = __float2bfloat16(p1);
                __nv_bfloat162 hp; hp.x = h0; hp.y = h1;
                __nv_bfloat162 lp;
                lp.x = __float2bfloat16(p0 - __bfloat162float(h0));
                lp.y = __float2bfloat16(p1 - __bfloat162float(h1));
                Pr_h[c >> 1] = hp;
                Pr_l[c >> 1] = lp;
            }
            m_s[r] = mn;
            l_s[r] = l;
            al_s[r] = alpha;
        }
        __syncthreads();

        // rescale O by alpha, then O += P V
        {
            const uint32_t* Ph32 = (const uint32_t*)Phs;
            const uint32_t* Pl32 = (const uint32_t*)Pls;
            const uint32_t* Vh32 = (const uint32_t*)Vhs;
            const uint32_t* Vl32 = (const uint32_t*)Vls;
#pragma unroll
            for (int mt = 0; mt < 2; ++mt) {
                int r = wm * 32 + mt * 16 + (lane >> 2);
                float aL = al_s[r];
                float aH = al_s[r + 8];
#pragma unroll
                for (int nt = 0; nt < 8; ++nt) {
                    O[mt][nt][0] *= aL; O[mt][nt][1] *= aL;
                    O[mt][nt][2] *= aH; O[mt][nt][3] *= aH;
                }
            }
#pragma unroll
            for (int k16 = 0; k16 < 4; ++k16) {
                const int cA = k16 * 8 + (lane & 3);
                uint32_t vbh[8][2], vbl[8][2];
#pragma unroll
                for (int nt = 0; nt < 8; ++nt) {
                    int n = wn * 64 + nt * 8 + (lane >> 2);
                    vbh[nt][0] = Vh32[n * VSTR32 + cA];
                    vbh[nt][1] = Vh32[n * VSTR32 + cA + 4];
                    vbl[nt][0] = Vl32[n * VSTR32 + cA];
                    vbl[nt][1] = Vl32[n * VSTR32 + cA + 4];
                }
#pragma unroll
                for (int mt = 0; mt < 2; ++mt) {
                    int r = wm * 32 + mt * 16 + (lane >> 2);
                    uint32_t pah[4], pal[4];
                    pah[0] = Ph32[r * PSTR32 + cA];
                    pah[1] = Ph32[(r + 8) * PSTR32 + cA];
                    pah[2] = Ph32[r * PSTR32 + cA + 4];
                    pah[3] = Ph32[(r + 8) * PSTR32 + cA + 4];
                    pal[0] = Pl32[r * PSTR32 + cA];
                    pal[1] = Pl32[(r + 8) * PSTR32 + cA];
                    pal[2] = Pl32[r * PSTR32 + cA + 4];
                    pal[3] = Pl32[(r + 8) * PSTR32 + cA + 4];
#pragma unroll
                    for (int nt = 0; nt < 8; ++nt) {
                        mma16816(O[mt][nt], pah, vbh[nt]);
                        mma16816(O[mt][nt], pah, vbl[nt]);
                        mma16816(O[mt][nt], pal, vbh[nt]);
                    }
                }
            }
        }
    }

    // epilogue: normalize and write y as bf16 hi/lo [b,t,C]
#pragma unroll
    for (int mt = 0; mt < 2; ++mt) {
        int rl = wm * 32 + mt * 16 + (lane >> 2);
        float invL = 1.0f / l_s[rl];
        float invH = 1.0f / l_s[rl + 8];
#pragma unroll
        for (int nt = 0; nt < 8; ++nt) {
            int d = wn * 64 + nt * 8 + 2 * (lane & 3);
            int col = h * HD + d;
#pragma unroll
            for (int half = 0; half < 2; ++half) {
                int t = qb * 128 + rl + half * 8;
                float v0 = O[mt][nt][half * 2 + 0] * (half ? invH : invL);
                float v1 = O[mt][nt][half * 2 + 1] * (half ? invH : invL);
                __nv_bfloat16 h0 = __float2bfloat16(v0);
                __nv_bfloat16 h1 = __float2bfloat16(v1);
                __nv_bfloat162 hp; hp.x = h0; hp.y = h1;
                __nv_bfloat162 lp;
                lp.x = __float2bfloat16(v0 - __bfloat162float(h0));
                lp.y = __float2bfloat16(v1 - __bfloat162float(h1));
                size_t dst = ((size_t)b * TT + t) * CC + col;
                *(__nv_bfloat162*)(yh + dst) = hp;
                *(__nv_bfloat162*)(yl + dst) = lp;
            }
        }
    }
}

// ---------------------------------------------------------------------------
extern "C" void kernel_launch(void* const* d_in, const int* in_sizes, int n_in,
                              void* d_out, int out_size) {
    const float* x = (const float*)d_in[0];
    const float* w_attn = (const float*)d_in[1];
    const float* w_proj = (const float*)d_in[2];
    float* out = (float*)d_out;

    float* qkv;
    __nv_bfloat16 *xh, *xl, *wah, *wal, *wph, *wpl, *yh, *yl;
    __nv_bfloat16 *aqh, *aql, *akh, *akl, *avh, *avl;
    cudaGetSymbolAddress((void**)&qkv, g_qkv);
    cudaGetSymbolAddress((void**)&xh, g_x_hi);
    cudaGetSymbolAddress((void**)&xl, g_x_lo);
    cudaGetSymbolAddress((void**)&wah, g_wa_hi);
    cudaGetSymbolAddress((void**)&wal, g_wa_lo);
    cudaGetSymbolAddress((void**)&wph, g_wp_hi);
    cudaGetSymbolAddress((void**)&wpl, g_wp_lo);
    cudaGetSymbolAddress((void**)&yh, g_y_hi);
    cudaGetSymbolAddress((void**)&yl, g_y_lo);
    cudaGetSymbolAddress((void**)&aqh, g_q_hi);
    cudaGetSymbolAddress((void**)&aql, g_q_lo);
    cudaGetSymbolAddress((void**)&akh, g_k_hi);
    cudaGetSymbolAddress((void**)&akl, g_k_lo);
    cudaGetSymbolAddress((void**)&avh, g_v_hi);
    cudaGetSymbolAddress((void**)&avl, g_v_lo);

    const int gemm_smem = 2 * 4 * TILE_HALFS * (int)sizeof(__nv_bfloat16);
    cudaFuncSetAttribute(gemm_bf16split, cudaFuncAttributeMaxDynamicSharedMemorySize, gemm_smem);
    cudaFuncSetAttribute(attn_tc, cudaFuncAttributeMaxDynamicSharedMemorySize, ATTN_SMEM);

    const int nx = BB * TT * CC;
    const int nwa = TC3 * CC;
    const int nwp = CC * CC;
    const int nhd = BB * HH * TT * HD;   // == nx

    split_kernel<<<(nx / 4 + 255) / 256, 256>>>(x, xh, xl, nx);
    split_kernel<<<(nwa / 4 + 255) / 256, 256>>>(w_attn, wah, wal, nwa);
    split_kernel<<<(nwp / 4 + 255) / 256, 256>>>(w_proj, wph, wpl, nwp);

    // 1) QKV projection
    gemm_bf16split<<<dim3(TC3 / GBN, (BB * TT) / GBM), 256, gemm_smem>>>(
        xh, xl, wah, wal, qkv, BB * TT, TC3, CC);

    // 2) split Q (scaled), K; split+transpose V
    const float scale = 0.08838834764831845f;  // 1/sqrt(128)
    split_qk<<<nhd / 4 / 256, 256>>>(qkv, aqh, aql, 0, scale);
    split_qk<<<nhd / 4 / 256, 256>>>(qkv, akh, akl, CC, 1.0f);
    split_v_T<<<dim3(TT / 32, HD / 32, BB * HH), 256>>>(qkv, avh, avl);

    // 3) tensor-core causal flash attention -> yh/yl
    attn_tc<<<dim3(TT / 128, BB * HH), 256, ATTN_SMEM>>>(
        aqh, aql, akh, akl, avh, avl, yh, yl);

    // 4) output projection
    gemm_bf16split<<<dim3(CC / GBN, (BB * TT) / GBM), 256, gemm_smem>>>(
        yh, yl, wph, wpl, out, BB * TT, CC, CC);
}